// round 7
// baseline (speedup 1.0000x reference)
#include <cuda_runtime.h>
#include <cuda_fp16.h>

#define NN 100000
#define EE 1600000
#define DH 64
#define SCAN_CH 98   // per-thread run: 1024*98 >= NN

// ---------------- scratch (device globals; no allocation allowed) ------------
__device__ __half g_h[NN * DH];      // fp16 feature rows for aggregation
__device__ float  g_bufB[NN * DH];
__device__ float  g_dinv[NN];
__device__ int    g_deg[NN];         // zero-initialized; re-zeroed by k_fill
__device__ int    g_off[NN + 1];
__device__ int    g_cur[NN];
__device__ int2   g_epack[EE];       // (src, coef-bits) sorted by dst bucket

// ---------------- 1: count degrees (4 edges/thread, bounded) -----------------
__global__ void k_count(const int* __restrict__ ei) {
    int t = blockIdx.x * blockDim.x + threadIdx.x;
    if (t >= EE / 4) return;                         // EE/4 = 400000 int4 records
    const int4* d4 = (const int4*)(ei + EE);
    int4 d = d4[t];
    atomicAdd(&g_deg[d.x], 1);
    atomicAdd(&g_deg[d.y], 1);
    atomicAdd(&g_deg[d.z], 1);
    atomicAdd(&g_deg[d.w], 1);
}

// ---------------- 2: single-block exclusive scan + dinv ----------------------
__global__ void k_scan() {
    int tid = threadIdx.x;
    int lane = tid & 31, wid = tid >> 5;
    int base = tid * SCAN_CH;

    // phase A: per-thread run sum
    int s = 0;
    for (int j = 0; j < SCAN_CH; j++) {
        int i = base + j;
        if (i < NN) s += g_deg[i];
    }
    // block exclusive scan of 1024 run sums
    int incl = s;
#pragma unroll
    for (int off = 1; off < 32; off <<= 1) {
        int t = __shfl_up_sync(0xFFFFFFFFu, incl, off);
        if (lane >= off) incl += t;
    }
    __shared__ int wsum[32], woff[32];
    if (lane == 31) wsum[wid] = incl;
    __syncthreads();
    if (tid < 32) {
        int v = wsum[tid];
        int iv = v;
#pragma unroll
        for (int off = 1; off < 32; off <<= 1) {
            int t = __shfl_up_sync(0xFFFFFFFFu, iv, off);
            if (tid >= off) iv += t;
        }
        woff[tid] = iv - v;
    }
    __syncthreads();

    // phase B: write offsets, cursors, dinv
    int run = woff[wid] + incl - s;
    for (int j = 0; j < SCAN_CH; j++) {
        int i = base + j;
        if (i < NN) {
            int d = g_deg[i];
            g_off[i] = run;
            g_cur[i] = run;
            g_dinv[i] = rsqrtf((float)d + 1.0f);
            run += d;
        }
    }
    if (tid == 0) g_off[NN] = EE;
}

// ---------------- 3: fill CSR buckets; re-zero deg for next call -------------
__global__ void k_fill(const int* __restrict__ ei) {
    int e = blockIdx.x * blockDim.x + threadIdx.x;
    if (e < NN) g_deg[e] = 0;            // deg dead after scan; reset for next call
    if (e >= EE) return;
    int s = ei[e];
    int d = ei[EE + e];
    int p = atomicAdd(&g_cur[d], 1);
    float c = g_dinv[s] * g_dinv[d];
    g_epack[p] = make_int2(s, __float_as_int(c));
}

// ---------------- aggregation: warp/node, masked unroll-8 pipeline -----------
__global__ void k_agg(const __half2* __restrict__ h, float* __restrict__ out,
                      const float* __restrict__ bias) {
    int w = (blockIdx.x * blockDim.x + threadIdx.x) >> 5;
    int lane = threadIdx.x & 31;
    if (w >= NN) return;
    int e = g_off[w];
    int end = g_off[w + 1];
    float a0 = 0.f, a1 = 0.f;

    while (e < end) {
        int2 p[8];
#pragma unroll
        for (int j = 0; j < 8; j++) {
            int idx = e + j;
            p[j] = g_epack[idx < end ? idx : end - 1];
        }
        __half2 r[8];
#pragma unroll
        for (int j = 0; j < 8; j++)
            r[j] = h[p[j].x * 32 + lane];
#pragma unroll
        for (int j = 0; j < 8; j++) {
            float c = (e + j < end) ? __int_as_float(p[j].y) : 0.f;
            float2 f = __half22float2(r[j]);
            a0 = fmaf(f.x, c, a0);
            a1 = fmaf(f.y, c, a1);
        }
        e += 8;
    }

    float dn = g_dinv[w];
    float d2 = dn * dn;
    float2 fs = __half22float2(h[w * 32 + lane]);
    a0 = fmaf(fs.x, d2, a0) + bias[2 * lane + 0];
    a1 = fmaf(fs.y, d2, a1) + bias[2 * lane + 1];
    float2 o;
    o.x = fmaxf(a0, 0.f);
    o.y = fmaxf(a1, 0.f);
    ((float2*)out)[(size_t)w * 32 + lane] = o;
}

// ---------------- GEMM 64x64 -> fp16 rows ------------------------------------
__global__ void k_gemm64(const float* __restrict__ X, const float* __restrict__ W,
                         __half* __restrict__ Y) {
    __shared__ float xs[64 * 64];
    __shared__ float wsm[64 * 64];
    int tid = threadIdx.x;
    int rowBlock = blockIdx.x * 64;

    const float4* W4 = (const float4*)W;
    float4* ws4 = (float4*)wsm;
#pragma unroll
    for (int i = tid; i < 1024; i += 256) ws4[i] = W4[i];

    float4* xs4 = (float4*)xs;
    const float4* X4 = (const float4*)X;
#pragma unroll
    for (int i = tid; i < 1024; i += 256) {
        int r = i >> 4;
        int gr = rowBlock + r;
        xs4[i] = (gr < NN) ? X4[(size_t)gr * 16 + (i & 15)]
                           : make_float4(0.f, 0.f, 0.f, 0.f);
    }
    __syncthreads();

    int cg = tid & 15;
    int r0 = (tid >> 4) * 4;
    float4 a0 = make_float4(0.f, 0.f, 0.f, 0.f), a1 = a0, a2 = a0, a3 = a0;

#pragma unroll
    for (int k = 0; k < 64; k++) {
        float4 w = ws4[k * 16 + cg];
        float x0 = xs[(r0 + 0) * 64 + k];
        float x1 = xs[(r0 + 1) * 64 + k];
        float x2 = xs[(r0 + 2) * 64 + k];
        float x3 = xs[(r0 + 3) * 64 + k];
        a0.x = fmaf(x0, w.x, a0.x); a0.y = fmaf(x0, w.y, a0.y);
        a0.z = fmaf(x0, w.z, a0.z); a0.w = fmaf(x0, w.w, a0.w);
        a1.x = fmaf(x1, w.x, a1.x); a1.y = fmaf(x1, w.y, a1.y);
        a1.z = fmaf(x1, w.z, a1.z); a1.w = fmaf(x1, w.w, a1.w);
        a2.x = fmaf(x2, w.x, a2.x); a2.y = fmaf(x2, w.y, a2.y);
        a2.z = fmaf(x2, w.z, a2.z); a2.w = fmaf(x2, w.w, a2.w);
        a3.x = fmaf(x3, w.x, a3.x); a3.y = fmaf(x3, w.y, a3.y);
        a3.z = fmaf(x3, w.z, a3.z); a3.w = fmaf(x3, w.w, a3.w);
    }

    float4 acc[4] = {a0, a1, a2, a3};
#pragma unroll
    for (int i = 0; i < 4; i++) {
        int gr = rowBlock + r0 + i;
        if (gr < NN) {
            float4 v = acc[i];
            __half2 h0 = __floats2half2_rn(v.x, v.y);
            __half2 h1 = __floats2half2_rn(v.z, v.w);
            uint2 u;
            u.x = *(unsigned int*)&h0;
            u.y = *(unsigned int*)&h1;
            ((uint2*)(Y + (size_t)gr * 64))[cg] = u;
        }
    }
}

// ---------------- fused FFN: relu(X@Wf1+bf1) @ Wf2 + bf2 ---------------------
__global__ void k_ffn(const float* __restrict__ X,
                      const float* __restrict__ W1f, const float* __restrict__ b1f,
                      const float* __restrict__ W2f, const float* __restrict__ b2f,
                      float* __restrict__ Y) {
    __shared__ float xs[64 * 64];
    __shared__ float wsm[64 * 64];
    __shared__ float w2s[64 * 16];
    __shared__ float bs1[64];
    __shared__ float bs2[16];
    int tid = threadIdx.x;
    int rowBlock = blockIdx.x * 64;

    const float4* W4 = (const float4*)W1f;
    float4* ws4 = (float4*)wsm;
#pragma unroll
    for (int i = tid; i < 1024; i += 256) ws4[i] = W4[i];
    if (tid < 256) ((float4*)w2s)[tid] = ((const float4*)W2f)[tid];
    if (tid < 64) bs1[tid] = b1f[tid];
    if (tid < 16) bs2[tid] = b2f[tid];

    float4* xs4 = (float4*)xs;
    const float4* X4 = (const float4*)X;
#pragma unroll
    for (int i = tid; i < 1024; i += 256) {
        int r = i >> 4;
        int gr = rowBlock + r;
        xs4[i] = (gr < NN) ? X4[(size_t)gr * 16 + (i & 15)]
                           : make_float4(0.f, 0.f, 0.f, 0.f);
    }
    __syncthreads();

    // phase 1: H = relu(X @ Wf1 + bf1), 4x4 register tile per thread
    int cg = tid & 15;
    int r0 = (tid >> 4) * 4;
    float4 a0 = make_float4(0.f, 0.f, 0.f, 0.f), a1 = a0, a2 = a0, a3 = a0;
#pragma unroll
    for (int k = 0; k < 64; k++) {
        float4 w = ws4[k * 16 + cg];
        float x0 = xs[(r0 + 0) * 64 + k];
        float x1 = xs[(r0 + 1) * 64 + k];
        float x2 = xs[(r0 + 2) * 64 + k];
        float x3 = xs[(r0 + 3) * 64 + k];
        a0.x = fmaf(x0, w.x, a0.x); a0.y = fmaf(x0, w.y, a0.y);
        a0.z = fmaf(x0, w.z, a0.z); a0.w = fmaf(x0, w.w, a0.w);
        a1.x = fmaf(x1, w.x, a1.x); a1.y = fmaf(x1, w.y, a1.y);
        a1.z = fmaf(x1, w.z, a1.z); a1.w = fmaf(x1, w.w, a1.w);
        a2.x = fmaf(x2, w.x, a2.x); a2.y = fmaf(x2, w.y, a2.y);
        a2.z = fmaf(x2, w.z, a2.z); a2.w = fmaf(x2, w.w, a2.w);
        a3.x = fmaf(x3, w.x, a3.x); a3.y = fmaf(x3, w.y, a3.y);
        a3.z = fmaf(x3, w.z, a3.z); a3.w = fmaf(x3, w.w, a3.w);
    }
    __syncthreads();   // xs reads done; reuse xs for H
    {
        float4 acc[4] = {a0, a1, a2, a3};
#pragma unroll
        for (int i = 0; i < 4; i++) {
            float4 v = acc[i];
            v.x = fmaxf(v.x + bs1[cg * 4 + 0], 0.f);
            v.y = fmaxf(v.y + bs1[cg * 4 + 1], 0.f);
            v.z = fmaxf(v.z + bs1[cg * 4 + 2], 0.f);
            v.w = fmaxf(v.w + bs1[cg * 4 + 3], 0.f);
            xs4[(r0 + i) * 16 + cg] = v;
        }
    }
    __syncthreads();

    // phase 2: Y = H @ Wf2 + bf2  (64x16)
    int row = tid >> 2;
    int c2 = tid & 3;
    float4 acc = make_float4(0.f, 0.f, 0.f, 0.f);
#pragma unroll
    for (int k = 0; k < 64; k++) {
        float4 w = ((float4*)w2s)[k * 4 + c2];
        float x = xs[row * 64 + k];
        acc.x = fmaf(x, w.x, acc.x);
        acc.y = fmaf(x, w.y, acc.y);
        acc.z = fmaf(x, w.z, acc.z);
        acc.w = fmaf(x, w.w, acc.w);
    }
    int gr = rowBlock + row;
    if (gr < NN) {
        acc.x += bs2[c2 * 4 + 0]; acc.y += bs2[c2 * 4 + 1];
        acc.z += bs2[c2 * 4 + 2]; acc.w += bs2[c2 * 4 + 3];
        ((float4*)Y)[(size_t)gr * 4 + c2] = acc;
    }
}

// ---------------- launch ------------------------------------------------------
extern "C" void kernel_launch(void* const* d_in, const int* in_sizes, int n_in,
                              void* d_out, int out_size) {
    const float* x   = (const float*)d_in[0];
    const int*   ei  = (const int*)d_in[1];
    const float* W1  = (const float*)d_in[2];
    const float* b1  = (const float*)d_in[3];
    const float* W2  = (const float*)d_in[4];
    const float* b2  = (const float*)d_in[5];
    const float* W3  = (const float*)d_in[6];
    const float* b3  = (const float*)d_in[7];
    const float* Wf1 = (const float*)d_in[8];
    const float* bf1 = (const float*)d_in[9];
    const float* Wf2 = (const float*)d_in[10];
    const float* bf2 = (const float*)d_in[11];
    float* out = (float*)d_out;

    void *pH_, *pB_;
    cudaGetSymbolAddress(&pH_, g_h);
    cudaGetSymbolAddress(&pB_, g_bufB);
    __half* H = (__half*)pH_;
    float* B = (float*)pB_;

    int nblkC  = (EE / 4 + 255) / 256;
    int nblkG  = (NN + 63) / 64;
    int nblkAgg = (NN * 32 + 255) / 256;
    int nblkF  = (EE + 255) / 256;

    // 1-3: graph preprocessing (structure shared by all 3 conv layers)
    k_count<<<nblkC, 256>>>(ei);
    k_scan<<<1, 1024>>>();
    k_fill<<<nblkF, 256>>>(ei);

    // 4: layer-1 GEMM  (ncu profiles launch #4)
    k_gemm64<<<nblkG, 256>>>(x, W1, H);
    k_agg<<<nblkAgg, 256>>>((const __half2*)H, B, b1);
    k_gemm64<<<nblkG, 256>>>(B, W2, H);
    k_agg<<<nblkAgg, 256>>>((const __half2*)H, B, b2);
    k_gemm64<<<nblkG, 256>>>(B, W3, H);
    k_agg<<<nblkAgg, 256>>>((const __half2*)H, B, b3);

    // 10: fused FFN
    k_ffn<<<nblkG, 256>>>(B, Wf1, bf1, Wf2, bf2, out);
}

// round 8
// speedup vs baseline: 1.8815x; 1.8815x over previous
#include <cuda_runtime.h>
#include <cuda_fp16.h>

#define NN 100000
#define EE 1600000
#define DH 64
#define NB_SCAN 98   // ceil(NN/1024)

// ---------------- scratch (device globals; no allocation allowed) ------------
__device__ __half g_h[NN * DH];      // gemm output rows (fp16), input to agg
__device__ __half g_f[NN * DH];      // agg output rows (fp16), input to next gemm / ffn
__device__ float  g_dinv[NN];
__device__ int    g_deg[NN];         // zero-initialized; re-zeroed by k_fill
__device__ int    g_off[NN + 1];
__device__ int    g_cur[NN];
__device__ int2   g_epack[EE];       // (src, coef-bits) sorted by dst bucket
__device__ int    g_bsum[128];
__device__ int    g_boff[128];

// ---------------- 1: count degrees (4 edges/thread, bounded) -----------------
__global__ void k_count(const int* __restrict__ ei) {
    int t = blockIdx.x * blockDim.x + threadIdx.x;
    if (t >= EE / 4) return;
    const int4* d4 = (const int4*)(ei + EE);
    int4 d = d4[t];
    atomicAdd(&g_deg[d.x], 1);
    atomicAdd(&g_deg[d.y], 1);
    atomicAdd(&g_deg[d.z], 1);
    atomicAdd(&g_deg[d.w], 1);
}

// ---------------- scan stage 1: per-1024-chunk sums (coalesced-ish) ----------
__global__ void k_s1() {
    int base = blockIdx.x * 1024 + threadIdx.x * 4;
    int s = 0;
#pragma unroll
    for (int j = 0; j < 4; j++) {
        int i = base + j;
        if (i < NN) s += g_deg[i];
    }
#pragma unroll
    for (int off = 16; off > 0; off >>= 1)
        s += __shfl_down_sync(0xFFFFFFFFu, s, off);
    __shared__ int ws[8];
    int wid = threadIdx.x >> 5, lane = threadIdx.x & 31;
    if (lane == 0) ws[wid] = s;
    __syncthreads();
    if (threadIdx.x == 0) {
        int t = 0;
#pragma unroll
        for (int w = 0; w < 8; w++) t += ws[w];
        g_bsum[blockIdx.x] = t;
    }
}

// ---------------- scan stage 2: exclusive scan of chunk sums -----------------
__global__ void k_s2() {
    __shared__ int sh[128];
    int tid = threadIdx.x;
    int v = (tid < NB_SCAN) ? g_bsum[tid] : 0;
    sh[tid] = v;
    __syncthreads();
    for (int off = 1; off < 128; off <<= 1) {
        int t = (tid >= off) ? sh[tid - off] : 0;
        __syncthreads();
        sh[tid] += t;
        __syncthreads();
    }
    if (tid < NB_SCAN) g_boff[tid] = sh[tid] - v;
    if (tid == 0) g_off[NN] = EE;
}

// ---------------- scan stage 3: within-chunk exclusive scan + dinv -----------
__global__ void k_s3() {
    int tid = threadIdx.x;
    int lane = tid & 31, wid = tid >> 5;
    int base = blockIdx.x * 1024 + tid * 4;
    int v[4];
    int s = 0;
#pragma unroll
    for (int j = 0; j < 4; j++) {
        int i = base + j;
        v[j] = (i < NN) ? g_deg[i] : 0;
        s += v[j];
    }
    int incl = s;
#pragma unroll
    for (int off = 1; off < 32; off <<= 1) {
        int t = __shfl_up_sync(0xFFFFFFFFu, incl, off);
        if (lane >= off) incl += t;
    }
    __shared__ int wsum[8], woff[8];
    if (lane == 31) wsum[wid] = incl;
    __syncthreads();
    if (tid == 0) {
        int run = 0;
#pragma unroll
        for (int w = 0; w < 8; w++) { woff[w] = run; run += wsum[w]; }
    }
    __syncthreads();
    int excl = g_boff[blockIdx.x] + woff[wid] + incl - s;
#pragma unroll
    for (int j = 0; j < 4; j++) {
        int i = base + j;
        if (i < NN) {
            g_off[i] = excl;
            g_cur[i] = excl;
            g_dinv[i] = rsqrtf((float)v[j] + 1.0f);
        }
        excl += v[j];
    }
}

// ---------------- fill CSR buckets; re-zero deg for next call ----------------
__global__ void k_fill(const int* __restrict__ ei) {
    int e = blockIdx.x * blockDim.x + threadIdx.x;
    if (e < NN) g_deg[e] = 0;
    if (e >= EE) return;
    int s = ei[e];
    int d = ei[EE + e];
    int p = atomicAdd(&g_cur[d], 1);
    float c = g_dinv[s] * g_dinv[d];
    g_epack[p] = make_int2(s, __float_as_int(c));
}

// ---------------- aggregation: warp/node, masked unroll-8, fp16 out ----------
__global__ void k_agg(const __half2* __restrict__ h, __half2* __restrict__ out,
                      const float* __restrict__ bias) {
    int w = (blockIdx.x * blockDim.x + threadIdx.x) >> 5;
    int lane = threadIdx.x & 31;
    if (w >= NN) return;
    int e = g_off[w];
    int end = g_off[w + 1];
    float a0 = 0.f, a1 = 0.f;

    while (e < end) {
        int2 p[8];
#pragma unroll
        for (int j = 0; j < 8; j++) {
            int idx = e + j;
            p[j] = g_epack[idx < end ? idx : end - 1];
        }
        __half2 r[8];
#pragma unroll
        for (int j = 0; j < 8; j++)
            r[j] = h[p[j].x * 32 + lane];
#pragma unroll
        for (int j = 0; j < 8; j++) {
            float c = (e + j < end) ? __int_as_float(p[j].y) : 0.f;
            float2 f = __half22float2(r[j]);
            a0 = fmaf(f.x, c, a0);
            a1 = fmaf(f.y, c, a1);
        }
        e += 8;
    }

    float dn = g_dinv[w];
    float d2 = dn * dn;
    float2 fs = __half22float2(h[w * 32 + lane]);
    a0 = fmaf(fs.x, d2, a0) + bias[2 * lane + 0];
    a1 = fmaf(fs.y, d2, a1) + bias[2 * lane + 1];
    out[(size_t)w * 32 + lane] = __floats2half2_rn(fmaxf(a0, 0.f), fmaxf(a1, 0.f));
}

// ---------------- tensor-core GEMM 64rows x 64cols x 64k ---------------------
// Y[m,n] = sum_k X[m,k] * W[k,n]; X fp32 (IN_FP32) or fp16; W fp32 -> fp16;
// Y fp16. mma.sync.m16n8k16 row.col, A from xs, B from wt (W transposed).
#define XS_STRIDE 72   // halfs; bank = qr*4 + qc/2 (+const) -> conflict-free frags
template <bool IN_FP32>
__global__ void k_gemm_tc(const void* __restrict__ Xv, const float* __restrict__ W,
                          __half* __restrict__ Y) {
    __shared__ __half xs[64 * XS_STRIDE];
    __shared__ __half wt[64 * XS_STRIDE];   // wt[n][k]
    int tid = threadIdx.x;
    int rowBlock = blockIdx.x * 64;

    // W[k][n] fp32 -> wt[n][k] fp16 (transpose)
    for (int i = tid; i < 1024; i += 256) {
        int k = i >> 4, c4 = (i & 15) * 4;
        float4 w = ((const float4*)W)[i];
        wt[(c4 + 0) * XS_STRIDE + k] = __float2half(w.x);
        wt[(c4 + 1) * XS_STRIDE + k] = __float2half(w.y);
        wt[(c4 + 2) * XS_STRIDE + k] = __float2half(w.z);
        wt[(c4 + 3) * XS_STRIDE + k] = __float2half(w.w);
    }

    // X rows -> xs fp16
    if (IN_FP32) {
        const float4* X4 = (const float4*)Xv;
        for (int i = tid; i < 1024; i += 256) {
            int r = i >> 4, c4 = (i & 15) * 4;
            int gr = rowBlock + r;
            float4 v = (gr < NN) ? X4[(size_t)gr * 16 + (i & 15)]
                                 : make_float4(0.f, 0.f, 0.f, 0.f);
            __half2 h0 = __floats2half2_rn(v.x, v.y);
            __half2 h1 = __floats2half2_rn(v.z, v.w);
            uint2 u;
            u.x = *(unsigned int*)&h0;
            u.y = *(unsigned int*)&h1;
            *(uint2*)&xs[r * XS_STRIDE + c4] = u;
        }
    } else {
        const uint2* X2 = (const uint2*)Xv;   // 4 halfs per uint2
        for (int i = tid; i < 1024; i += 256) {
            int r = i >> 4, c4 = (i & 15) * 4;
            int gr = rowBlock + r;
            uint2 u = (gr < NN) ? X2[(size_t)gr * 16 + (i & 15)] : make_uint2(0u, 0u);
            *(uint2*)&xs[r * XS_STRIDE + c4] = u;
        }
    }
    __syncthreads();

    int lane = tid & 31, wid = tid >> 5;
    int mt = (wid & 3) * 16;        // warp's m-tile base row
    int ng = (wid >> 2) * 32;       // warp's n-group base col
    int qr = lane >> 2;             // 0..7
    int qc = (lane & 3) * 2;        // 0,2,4,6
    float c[4][4] = {{0.f}};

#pragma unroll
    for (int ks = 0; ks < 4; ks++) {
        int k0 = ks * 16;
        unsigned int a0 = *(unsigned int*)&xs[(mt + qr) * XS_STRIDE + k0 + qc];
        unsigned int a1 = *(unsigned int*)&xs[(mt + qr + 8) * XS_STRIDE + k0 + qc];
        unsigned int a2 = *(unsigned int*)&xs[(mt + qr) * XS_STRIDE + k0 + qc + 8];
        unsigned int a3 = *(unsigned int*)&xs[(mt + qr + 8) * XS_STRIDE + k0 + qc + 8];
#pragma unroll
        for (int j = 0; j < 4; j++) {
            int n0 = ng + j * 8;
            unsigned int b0 = *(unsigned int*)&wt[(n0 + qr) * XS_STRIDE + k0 + qc];
            unsigned int b1 = *(unsigned int*)&wt[(n0 + qr) * XS_STRIDE + k0 + qc + 8];
            asm volatile(
                "mma.sync.aligned.m16n8k16.row.col.f32.f16.f16.f32 "
                "{%0,%1,%2,%3}, {%4,%5,%6,%7}, {%8,%9}, {%0,%1,%2,%3};"
                : "+f"(c[j][0]), "+f"(c[j][1]), "+f"(c[j][2]), "+f"(c[j][3])
                : "r"(a0), "r"(a1), "r"(a2), "r"(a3), "r"(b0), "r"(b1));
        }
    }

    int gr0 = rowBlock + mt + qr;
    int gr1 = gr0 + 8;
#pragma unroll
    for (int j = 0; j < 4; j++) {
        int n0 = ng + j * 8;
        __half2 h01 = __floats2half2_rn(c[j][0], c[j][1]);
        __half2 h23 = __floats2half2_rn(c[j][2], c[j][3]);
        if (gr0 < NN) *(__half2*)&Y[(size_t)gr0 * 64 + n0 + qc] = h01;
        if (gr1 < NN) *(__half2*)&Y[(size_t)gr1 * 64 + n0 + qc] = h23;
    }
}

// ---------------- fused FFN: relu(X@Wf1+bf1) @ Wf2 + bf2  (X fp16) -----------
__global__ void k_ffn(const __half* __restrict__ Xh,
                      const float* __restrict__ W1f, const float* __restrict__ b1f,
                      const float* __restrict__ W2f, const float* __restrict__ b2f,
                      float* __restrict__ Y) {
    __shared__ float xs[64 * 64];
    __shared__ float wsm[64 * 64];
    __shared__ float w2s[64 * 16];
    __shared__ float bs1[64];
    __shared__ float bs2[16];
    int tid = threadIdx.x;
    int rowBlock = blockIdx.x * 64;

    const float4* W4 = (const float4*)W1f;
    float4* ws4 = (float4*)wsm;
#pragma unroll
    for (int i = tid; i < 1024; i += 256) ws4[i] = W4[i];
    if (tid < 256) ((float4*)w2s)[tid] = ((const float4*)W2f)[tid];
    if (tid < 64) bs1[tid] = b1f[tid];
    if (tid < 16) bs2[tid] = b2f[tid];

    float4* xs4 = (float4*)xs;
    const uint2* X2 = (const uint2*)Xh;
#pragma unroll
    for (int i = tid; i < 1024; i += 256) {
        int r = i >> 4;
        int gr = rowBlock + r;
        float4 v;
        if (gr < NN) {
            uint2 u = X2[(size_t)gr * 16 + (i & 15)];
            float2 f0 = __half22float2(*(__half2*)&u.x);
            float2 f1 = __half22float2(*(__half2*)&u.y);
            v = make_float4(f0.x, f0.y, f1.x, f1.y);
        } else {
            v = make_float4(0.f, 0.f, 0.f, 0.f);
        }
        xs4[i] = v;
    }
    __syncthreads();

    // phase 1: H = relu(X @ Wf1 + bf1)
    int cg = tid & 15;
    int r0 = (tid >> 4) * 4;
    float4 a0 = make_float4(0.f, 0.f, 0.f, 0.f), a1 = a0, a2 = a0, a3 = a0;
#pragma unroll
    for (int k = 0; k < 64; k++) {
        float4 w = ws4[k * 16 + cg];
        float x0 = xs[(r0 + 0) * 64 + k];
        float x1 = xs[(r0 + 1) * 64 + k];
        float x2 = xs[(r0 + 2) * 64 + k];
        float x3 = xs[(r0 + 3) * 64 + k];
        a0.x = fmaf(x0, w.x, a0.x); a0.y = fmaf(x0, w.y, a0.y);
        a0.z = fmaf(x0, w.z, a0.z); a0.w = fmaf(x0, w.w, a0.w);
        a1.x = fmaf(x1, w.x, a1.x); a1.y = fmaf(x1, w.y, a1.y);
        a1.z = fmaf(x1, w.z, a1.z); a1.w = fmaf(x1, w.w, a1.w);
        a2.x = fmaf(x2, w.x, a2.x); a2.y = fmaf(x2, w.y, a2.y);
        a2.z = fmaf(x2, w.z, a2.z); a2.w = fmaf(x2, w.w, a2.w);
        a3.x = fmaf(x3, w.x, a3.x); a3.y = fmaf(x3, w.y, a3.y);
        a3.z = fmaf(x3, w.z, a3.z); a3.w = fmaf(x3, w.w, a3.w);
    }
    __syncthreads();
    {
        float4 acc[4] = {a0, a1, a2, a3};
#pragma unroll
        for (int i = 0; i < 4; i++) {
            float4 v = acc[i];
            v.x = fmaxf(v.x + bs1[cg * 4 + 0], 0.f);
            v.y = fmaxf(v.y + bs1[cg * 4 + 1], 0.f);
            v.z = fmaxf(v.z + bs1[cg * 4 + 2], 0.f);
            v.w = fmaxf(v.w + bs1[cg * 4 + 3], 0.f);
            xs4[(r0 + i) * 16 + cg] = v;
        }
    }
    __syncthreads();

    // phase 2: Y = H @ Wf2 + bf2
    int row = tid >> 2;
    int c2 = tid & 3;
    float4 acc = make_float4(0.f, 0.f, 0.f, 0.f);
#pragma unroll
    for (int k = 0; k < 64; k++) {
        float4 w = ((float4*)w2s)[k * 4 + c2];
        float x = xs[row * 64 + k];
        acc.x = fmaf(x, w.x, acc.x);
        acc.y = fmaf(x, w.y, acc.y);
        acc.z = fmaf(x, w.z, acc.z);
        acc.w = fmaf(x, w.w, acc.w);
    }
    int gr = rowBlock + row;
    if (gr < NN) {
        acc.x += bs2[c2 * 4 + 0]; acc.y += bs2[c2 * 4 + 1];
        acc.z += bs2[c2 * 4 + 2]; acc.w += bs2[c2 * 4 + 3];
        ((float4*)Y)[(size_t)gr * 4 + c2] = acc;
    }
}

// ---------------- launch ------------------------------------------------------
extern "C" void kernel_launch(void* const* d_in, const int* in_sizes, int n_in,
                              void* d_out, int out_size) {
    const float* x   = (const float*)d_in[0];
    const int*   ei  = (const int*)d_in[1];
    const float* W1  = (const float*)d_in[2];
    const float* b1  = (const float*)d_in[3];
    const float* W2  = (const float*)d_in[4];
    const float* b2  = (const float*)d_in[5];
    const float* W3  = (const float*)d_in[6];
    const float* b3  = (const float*)d_in[7];
    const float* Wf1 = (const float*)d_in[8];
    const float* bf1 = (const float*)d_in[9];
    const float* Wf2 = (const float*)d_in[10];
    const float* bf2 = (const float*)d_in[11];
    float* out = (float*)d_out;

    void *pH_, *pF_;
    cudaGetSymbolAddress(&pH_, g_h);
    cudaGetSymbolAddress(&pF_, g_f);
    __half* H = (__half*)pH_;
    __half* F = (__half*)pF_;

    int nblkC   = (EE / 4 + 255) / 256;
    int nblkG   = (NN + 63) / 64;
    int nblkAgg = (NN * 32 + 255) / 256;
    int nblkF   = (EE + 255) / 256;

    // preprocessing (structure shared by all 3 conv layers)
    k_count<<<nblkC, 256>>>(ei);
    k_s1<<<NB_SCAN, 256>>>();
    k_s2<<<1, 128>>>();
    // layer-1 GEMM is graph-independent; placed here so ncu (launch #4) profiles it
    k_gemm_tc<true><<<nblkG, 256>>>(x, W1, H);
    k_s3<<<NB_SCAN, 256>>>();
    k_fill<<<nblkF, 256>>>(ei);

    // layer 1 aggregate
    k_agg<<<nblkAgg, 256>>>((const __half2*)H, (__half2*)F, b1);
    // layer 2
    k_gemm_tc<false><<<nblkG, 256>>>(F, W2, H);
    k_agg<<<nblkAgg, 256>>>((const __half2*)H, (__half2*)F, b2);
    // layer 3
    k_gemm_tc<false><<<nblkG, 256>>>(F, W3, H);
    k_agg<<<nblkAgg, 256>>>((const __half2*)H, (__half2*)F, b3);

    // fused FFN
    k_ffn<<<nblkG, 256>>>(F, Wf1, bf1, Wf2, bf2, out);
}

// round 10
// speedup vs baseline: 2.2350x; 1.1879x over previous
#include <cuda_runtime.h>
#include <cuda_fp16.h>

#define NN 100000
#define EE 1600000
#define DH 64
#define NB_SCAN 98     // ceil(NN/1024)
#define WT_STRIDE 72   // halfs; keeps mma fragment loads bank-conflict-free
#define WT_SZ (64 * WT_STRIDE)

// ---------------- scratch (device globals; no allocation allowed) ------------
__device__ __half g_h[NN * DH];      // gemm output rows (fp16), input to agg
__device__ __half g_f[NN * DH];      // agg output rows (fp16), input to next gemm / ffn
__device__ __half g_wt[5 * WT_SZ];   // pre-transposed fp16 weights: [w][n*72+k]
__device__ float  g_dinv[NN];
__device__ int    g_deg[NN];         // zero-initialized; re-zeroed by k_fill
__device__ int    g_off[NN + 1];
__device__ int    g_cur[NN];
__device__ int2   g_epack[EE];       // (src, coef-bits) sorted by dst bucket
__device__ int    g_bsum[128];

// ---------------- weight prep: fp32 [k][n] -> fp16 wt[n][k] stride 72 --------
__global__ void k_wprep(const float* __restrict__ W1, const float* __restrict__ W2,
                        const float* __restrict__ W3, const float* __restrict__ Wf1,
                        const float* __restrict__ Wf2) {
    int t = blockIdx.x * blockDim.x + threadIdx.x;
    if (t < 4 * 4096) {
        int w = t >> 12, i = t & 4095, k = i >> 6, n = i & 63;
        const float* src = (w == 0) ? W1 : (w == 1) ? W2 : (w == 2) ? W3 : Wf1;
        g_wt[w * WT_SZ + n * WT_STRIDE + k] = __float2half(src[k * 64 + n]);
    } else if (t < 4 * 4096 + 1024) {
        int i = t - 4 * 4096;
        int k = i >> 4, n = i & 15;
        g_wt[4 * WT_SZ + n * WT_STRIDE + k] = __float2half(Wf2[k * 16 + n]);
    }
}

// ---------------- count degrees (4 edges/thread, bounded) --------------------
__global__ void k_count(const int* __restrict__ ei) {
    int t = blockIdx.x * blockDim.x + threadIdx.x;
    if (t >= EE / 4) return;
    const int4* d4 = (const int4*)(ei + EE);
    int4 d = d4[t];
    atomicAdd(&g_deg[d.x], 1);
    atomicAdd(&g_deg[d.y], 1);
    atomicAdd(&g_deg[d.z], 1);
    atomicAdd(&g_deg[d.w], 1);
}

// ---------------- scan stage 1: per-1024-chunk sums --------------------------
__global__ void k_s1() {
    int base = blockIdx.x * 1024 + threadIdx.x * 4;
    int s = 0;
#pragma unroll
    for (int j = 0; j < 4; j++) {
        int i = base + j;
        if (i < NN) s += g_deg[i];
    }
#pragma unroll
    for (int off = 16; off > 0; off >>= 1)
        s += __shfl_down_sync(0xFFFFFFFFu, s, off);
    __shared__ int ws[8];
    int wid = threadIdx.x >> 5, lane = threadIdx.x & 31;
    if (lane == 0) ws[wid] = s;
    __syncthreads();
    if (threadIdx.x == 0) {
        int t = 0;
#pragma unroll
        for (int w = 0; w < 8; w++) t += ws[w];
        g_bsum[blockIdx.x] = t;
    }
}

// ---------------- scan stage 3 (merged s2): chunk scan + dinv ----------------
__global__ void k_s3() {
    int tid = threadIdx.x;
    int lane = tid & 31, wid = tid >> 5;
    int base = blockIdx.x * 1024 + tid * 4;
    __shared__ int bsh[NB_SCAN];
    if (tid < NB_SCAN) bsh[tid] = g_bsum[tid];

    int v[4];
    int s = 0;
#pragma unroll
    for (int j = 0; j < 4; j++) {
        int i = base + j;
        v[j] = (i < NN) ? g_deg[i] : 0;
        s += v[j];
    }
    int incl = s;
#pragma unroll
    for (int off = 1; off < 32; off <<= 1) {
        int t = __shfl_up_sync(0xFFFFFFFFu, incl, off);
        if (lane >= off) incl += t;
    }
    __shared__ int wsum[8], woff[8], chunkOff;
    if (lane == 31) wsum[wid] = incl;
    __syncthreads();
    if (tid == 0) {
        int run = 0;
#pragma unroll
        for (int w = 0; w < 8; w++) { woff[w] = run; run += wsum[w]; }
        int co = 0;
        for (int b = 0; b < blockIdx.x; b++) co += bsh[b];
        chunkOff = co;
    }
    __syncthreads();
    int excl = chunkOff + woff[wid] + incl - s;
#pragma unroll
    for (int j = 0; j < 4; j++) {
        int i = base + j;
        if (i < NN) {
            g_off[i] = excl;
            g_cur[i] = excl;
            g_dinv[i] = rsqrtf((float)v[j] + 1.0f);
        }
        excl += v[j];
    }
    if (blockIdx.x == 0 && tid == 0) g_off[NN] = EE;
}

// ---------------- fill CSR buckets; re-zero deg for next call ----------------
__global__ void k_fill(const int* __restrict__ ei) {
    int e = blockIdx.x * blockDim.x + threadIdx.x;
    if (e < NN) g_deg[e] = 0;
    if (e >= EE) return;
    int s = ei[e];
    int d = ei[EE + e];
    int p = atomicAdd(&g_cur[d], 1);
    float c = g_dinv[s] * g_dinv[d];
    g_epack[p] = make_int2(s, __float_as_int(c));
}

// ---------------- aggregation: warp/node, masked unroll-8, fp16 out ----------
__global__ void k_agg(const __half2* __restrict__ h, __half2* __restrict__ out,
                      const float* __restrict__ bias) {
    int w = (blockIdx.x * blockDim.x + threadIdx.x) >> 5;
    int lane = threadIdx.x & 31;
    if (w >= NN) return;
    int e = g_off[w];
    int end = g_off[w + 1];
    float a0 = 0.f, a1 = 0.f;

    while (e < end) {
        int2 p[8];
#pragma unroll
        for (int j = 0; j < 8; j++) {
            int idx = e + j;
            p[j] = g_epack[idx < end ? idx : end - 1];
        }
        __half2 r[8];
#pragma unroll
        for (int j = 0; j < 8; j++)
            r[j] = h[p[j].x * 32 + lane];
#pragma unroll
        for (int j = 0; j < 8; j++) {
            float c = (e + j < end) ? __int_as_float(p[j].y) : 0.f;
            float2 f = __half22float2(r[j]);
            a0 = fmaf(f.x, c, a0);
            a1 = fmaf(f.y, c, a1);
        }
        e += 8;
    }

    float dn = g_dinv[w];
    float d2 = dn * dn;
    float2 fs = __half22float2(h[w * 32 + lane]);
    a0 = fmaf(fs.x, d2, a0) + bias[2 * lane + 0];
    a1 = fmaf(fs.y, d2, a1) + bias[2 * lane + 1];
    out[(size_t)w * 32 + lane] = __floats2half2_rn(fmaxf(a0, 0.f), fmaxf(a1, 0.f));
}

// ---------------- TC GEMM: 128 rows/block, Y[m,n]=sum_k X[m,k] W[k,n] --------
// wt: pre-transposed fp16 [n][k] stride 72. Warp w computes rows w*16..w*16+15,
// all 64 cols (8 n-tiles x 4 k-steps of m16n8k16). Y fp16.
template <bool IN_FP32>
__global__ void k_gemm_tc(const void* __restrict__ Xv, const __half* __restrict__ wtg,
                          __half* __restrict__ Y) {
    __shared__ __half xs[128 * WT_STRIDE];
    __shared__ __half wt[WT_SZ];
    int tid = threadIdx.x;
    int rowBlock = blockIdx.x * 128;

    // copy pre-transposed W (9216B) via uint4
    const uint4* wsrc = (const uint4*)wtg;
#pragma unroll
    for (int i = tid; i < WT_SZ / 8; i += 256) ((uint4*)wt)[i] = wsrc[i];

    // X rows -> xs fp16 (stride 72)
    if (IN_FP32) {
        const float4* X4 = (const float4*)Xv;
        for (int i = tid; i < 2048; i += 256) {
            int r = i >> 4, c4 = (i & 15) * 4;
            int gr = rowBlock + r;
            float4 v = (gr < NN) ? X4[(size_t)gr * 16 + (i & 15)]
                                 : make_float4(0.f, 0.f, 0.f, 0.f);
            __half2 h0 = __floats2half2_rn(v.x, v.y);
            __half2 h1 = __floats2half2_rn(v.z, v.w);
            uint2 u;
            u.x = *(unsigned int*)&h0;
            u.y = *(unsigned int*)&h1;
            *(uint2*)&xs[r * WT_STRIDE + c4] = u;
        }
    } else {
        const uint2* X2 = (const uint2*)Xv;
        for (int i = tid; i < 2048; i += 256) {
            int r = i >> 4, c4 = (i & 15) * 4;
            int gr = rowBlock + r;
            uint2 u = (gr < NN) ? X2[(size_t)gr * 16 + (i & 15)] : make_uint2(0u, 0u);
            *(uint2*)&xs[r * WT_STRIDE + c4] = u;
        }
    }
    __syncthreads();

    int lane = tid & 31, w = tid >> 5;
    int mt = w * 16;
    int qr = lane >> 2;
    int qc = (lane & 3) * 2;
    float c[8][4];
#pragma unroll
    for (int j = 0; j < 8; j++)
#pragma unroll
        for (int q = 0; q < 4; q++) c[j][q] = 0.f;

#pragma unroll
    for (int ks = 0; ks < 4; ks++) {
        int k0 = ks * 16;
        unsigned int a0 = *(unsigned int*)&xs[(mt + qr) * WT_STRIDE + k0 + qc];
        unsigned int a1 = *(unsigned int*)&xs[(mt + qr + 8) * WT_STRIDE + k0 + qc];
        unsigned int a2 = *(unsigned int*)&xs[(mt + qr) * WT_STRIDE + k0 + qc + 8];
        unsigned int a3 = *(unsigned int*)&xs[(mt + qr + 8) * WT_STRIDE + k0 + qc + 8];
#pragma unroll
        for (int j = 0; j < 8; j++) {
            int n0 = j * 8;
            unsigned int b0 = *(unsigned int*)&wt[(n0 + qr) * WT_STRIDE + k0 + qc];
            unsigned int b1 = *(unsigned int*)&wt[(n0 + qr) * WT_STRIDE + k0 + qc + 8];
            asm volatile(
                "mma.sync.aligned.m16n8k16.row.col.f32.f16.f16.f32 "
                "{%0,%1,%2,%3}, {%4,%5,%6,%7}, {%8,%9}, {%0,%1,%2,%3};"
                : "+f"(c[j][0]), "+f"(c[j][1]), "+f"(c[j][2]), "+f"(c[j][3])
                : "r"(a0), "r"(a1), "r"(a2), "r"(a3), "r"(b0), "r"(b1));
        }
    }

    int gr0 = rowBlock + mt + qr;
    int gr1 = gr0 + 8;
#pragma unroll
    for (int j = 0; j < 8; j++) {
        int n0 = j * 8;
        if (gr0 < NN)
            *(__half2*)&Y[(size_t)gr0 * 64 + n0 + qc] = __floats2half2_rn(c[j][0], c[j][1]);
        if (gr1 < NN)
            *(__half2*)&Y[(size_t)gr1 * 64 + n0 + qc] = __floats2half2_rn(c[j][2], c[j][3]);
    }
}

// ---------------- TC fused FFN: relu(X@Wf1+bf1) @ Wf2 + bf2 ------------------
__global__ void k_ffn_tc(const __half* __restrict__ Xh,
                         const __half* __restrict__ wt1g, const __half* __restrict__ wt2g,
                         const float* __restrict__ b1f, const float* __restrict__ b2f,
                         float* __restrict__ Y) {
    __shared__ __half xs[128 * WT_STRIDE];
    __shared__ __half w1s[WT_SZ];
    __shared__ __half w2s[16 * WT_STRIDE];
    __shared__ float bs1[64], bs2[16];
    int tid = threadIdx.x;
    int rowBlock = blockIdx.x * 128;

#pragma unroll
    for (int i = tid; i < WT_SZ / 8; i += 256) ((uint4*)w1s)[i] = ((const uint4*)wt1g)[i];
    if (tid < (16 * WT_STRIDE) / 8) ((uint4*)w2s)[tid] = ((const uint4*)wt2g)[tid];
    if (tid < 64) bs1[tid] = b1f[tid];
    if (tid < 16) bs2[tid] = b2f[tid];

    const uint2* X2 = (const uint2*)Xh;
    for (int i = tid; i < 2048; i += 256) {
        int r = i >> 4, c4 = (i & 15) * 4;
        int gr = rowBlock + r;
        uint2 u = (gr < NN) ? X2[(size_t)gr * 16 + (i & 15)] : make_uint2(0u, 0u);
        *(uint2*)&xs[r * WT_STRIDE + c4] = u;
    }
    __syncthreads();

    int lane = tid & 31, w = tid >> 5;
    int mt = w * 16;
    int qr = lane >> 2;
    int qc = (lane & 3) * 2;

    // phase 1: H = X @ Wf1
    float c[8][4];
#pragma unroll
    for (int j = 0; j < 8; j++)
#pragma unroll
        for (int q = 0; q < 4; q++) c[j][q] = 0.f;
#pragma unroll
    for (int ks = 0; ks < 4; ks++) {
        int k0 = ks * 16;
        unsigned int a0 = *(unsigned int*)&xs[(mt + qr) * WT_STRIDE + k0 + qc];
        unsigned int a1 = *(unsigned int*)&xs[(mt + qr + 8) * WT_STRIDE + k0 + qc];
        unsigned int a2 = *(unsigned int*)&xs[(mt + qr) * WT_STRIDE + k0 + qc + 8];
        unsigned int a3 = *(unsigned int*)&xs[(mt + qr + 8) * WT_STRIDE + k0 + qc + 8];
#pragma unroll
        for (int j = 0; j < 8; j++) {
            int n0 = j * 8;
            unsigned int b0 = *(unsigned int*)&w1s[(n0 + qr) * WT_STRIDE + k0 + qc];
            unsigned int b1 = *(unsigned int*)&w1s[(n0 + qr) * WT_STRIDE + k0 + qc + 8];
            asm volatile(
                "mma.sync.aligned.m16n8k16.row.col.f32.f16.f16.f32 "
                "{%0,%1,%2,%3}, {%4,%5,%6,%7}, {%8,%9}, {%0,%1,%2,%3};"
                : "+f"(c[j][0]), "+f"(c[j][1]), "+f"(c[j][2]), "+f"(c[j][3])
                : "r"(a0), "r"(a1), "r"(a2), "r"(a3), "r"(b0), "r"(b1));
        }
    }

    // bias + relu -> back into xs (warp-private rows; only cross-lane within warp)
    __syncwarp();
#pragma unroll
    for (int j = 0; j < 8; j++) {
        int n0 = j * 8;
        float v0 = fmaxf(c[j][0] + bs1[n0 + qc], 0.f);
        float v1 = fmaxf(c[j][1] + bs1[n0 + qc + 1], 0.f);
        float v2 = fmaxf(c[j][2] + bs1[n0 + qc], 0.f);
        float v3 = fmaxf(c[j][3] + bs1[n0 + qc + 1], 0.f);
        *(__half2*)&xs[(mt + qr) * WT_STRIDE + n0 + qc] = __floats2half2_rn(v0, v1);
        *(__half2*)&xs[(mt + qr + 8) * WT_STRIDE + n0 + qc] = __floats2half2_rn(v2, v3);
    }
    __syncwarp();

    // phase 2: Y = H @ Wf2 + bf2  (n = 16)
    float d[2][4];
#pragma unroll
    for (int j = 0; j < 2; j++)
#pragma unroll
        for (int q = 0; q < 4; q++) d[j][q] = 0.f;
#pragma unroll
    for (int ks = 0; ks < 4; ks++) {
        int k0 = ks * 16;
        unsigned int a0 = *(unsigned int*)&xs[(mt + qr) * WT_STRIDE + k0 + qc];
        unsigned int a1 = *(unsigned int*)&xs[(mt + qr + 8) * WT_STRIDE + k0 + qc];
        unsigned int a2 = *(unsigned int*)&xs[(mt + qr) * WT_STRIDE + k0 + qc + 8];
        unsigned int a3 = *(unsigned int*)&xs[(mt + qr + 8) * WT_STRIDE + k0 + qc + 8];
#pragma unroll
        for (int j = 0; j < 2; j++) {
            int n0 = j * 8;
            unsigned int b0 = *(unsigned int*)&w2s[(n0 + qr) * WT_STRIDE + k0 + qc];
            unsigned int b1 = *(unsigned int*)&w2s[(n0 + qr) * WT_STRIDE + k0 + qc + 8];
            asm volatile(
                "mma.sync.aligned.m16n8k16.row.col.f32.f16.f16.f32 "
                "{%0,%1,%2,%3}, {%4,%5,%6,%7}, {%8,%9}, {%0,%1,%2,%3};"
                : "+f"(d[j][0]), "+f"(d[j][1]), "+f"(d[j][2]), "+f"(d[j][3])
                : "r"(a0), "r"(a1), "r"(a2), "r"(a3), "r"(b0), "r"(b1));
        }
    }

    int gr0 = rowBlock + mt + qr;
    int gr1 = gr0 + 8;
#pragma unroll
    for (int j = 0; j < 2; j++) {
        int n0 = j * 8;
        if (gr0 < NN) {
            float2 o = make_float2(d[j][0] + bs2[n0 + qc], d[j][1] + bs2[n0 + qc + 1]);
            *(float2*)&Y[(size_t)gr0 * 16 + n0 + qc] = o;
        }
        if (gr1 < NN) {
            float2 o = make_float2(d[j][2] + bs2[n0 + qc], d[j][3] + bs2[n0 + qc + 1]);
            *(float2*)&Y[(size_t)gr1 * 16 + n0 + qc] = o;
        }
    }
}

// ---------------- launch ------------------------------------------------------
extern "C" void kernel_launch(void* const* d_in, const int* in_sizes, int n_in,
                              void* d_out, int out_size) {
    const float* x   = (const float*)d_in[0];
    const int*   ei  = (const int*)d_in[1];
    const float* W1  = (const float*)d_in[2];
    const float* b1  = (const float*)d_in[3];
    const float* W2  = (const float*)d_in[4];
    const float* b2  = (const float*)d_in[5];
    const float* W3  = (const float*)d_in[6];
    const float* b3  = (const float*)d_in[7];
    const float* Wf1 = (const float*)d_in[8];
    const float* bf1 = (const float*)d_in[9];
    const float* Wf2 = (const float*)d_in[10];
    const float* bf2 = (const float*)d_in[11];
    float* out = (float*)d_out;

    void *pH_, *pF_, *pW_;
    cudaGetSymbolAddress(&pH_, g_h);
    cudaGetSymbolAddress(&pF_, g_f);
    cudaGetSymbolAddress(&pW_, g_wt);
    __half* H = (__half*)pH_;
    __half* F = (__half*)pF_;
    const __half* WT = (const __half*)pW_;

    int nblkC   = (EE / 4 + 255) / 256;
    int nblkG   = (NN + 127) / 128;
    int nblkAgg = (NN * 32 + 255) / 256;
    int nblkF   = (EE + 255) / 256;
    int nblkW   = (5 * 4096 + 255) / 256;

    // preprocessing
    k_wprep<<<nblkW, 256>>>(W1, W2, W3, Wf1, Wf2);
    k_count<<<nblkC, 256>>>(ei);
    k_s1<<<NB_SCAN, 256>>>();
    // layer-1 GEMM is graph-independent; launch #4 for ncu
    k_gemm_tc<true><<<nblkG, 256>>>(x, WT + 0 * WT_SZ, H);
    k_s3<<<NB_SCAN, 256>>>();
    k_fill<<<nblkF, 256>>>(ei);

    // layer 1 aggregate
    k_agg<<<nblkAgg, 256>>>((const __half2*)H, (__half2*)F, b1);
    // layer 2
    k_gemm_tc<false><<<nblkG, 256>>>(F, WT + 1 * WT_SZ, H);
    k_agg<<<nblkAgg, 256>>>((const __half2*)H, (__half2*)F, b2);
    // layer 3
    k_gemm_tc<false><<<nblkG, 256>>>(F, WT + 2 * WT_SZ, H);
    k_agg<<<nblkAgg, 256>>>((const __half2*)H, (__half2*)F, b3);

    // fused FFN
    k_ffn_tc<<<nblkG, 256>>>(F, WT + 3 * WT_SZ, WT + 4 * WT_SZ, bf1, bf2, out);
}